// round 9
// baseline (speedup 1.0000x reference)
#include <cuda_runtime.h>
#include <cuda_bf16.h>
#include <cuda_pipeline.h>
#include <mma.h>
using namespace nvcuda;

// ---------------------------------------------------------------------------
// Swin window-attention block, B=4, C=192, H=W=256, WS=8, SS=4, heads=8, hd=24
// bf16 tensor-core GEMMs (fp32 residual path), 3-stage cp.async, BM=256.
// (Resubmission of round-8 kernel — infra failure, never benched.)
// ---------------------------------------------------------------------------

// Scratch (device globals; no allocation at launch time)
__device__ __align__(128) float         g_xh  [50331648];   // shortcut (fp32), NHWC spatial
__device__ __align__(128) float         g_xh2 [50331648];   // x + attn (fp32), NHWC spatial
__device__ __align__(128) __nv_bfloat16 g_h   [50331648];   // LN'd activations (bf16)
__device__ __align__(128) __nv_bfloat16 g_qkv [150994944];  // qkv (bf16), window-token order
__device__ __align__(128) __nv_bfloat16 g_attn[50331648];   // attn out (bf16), window order
__device__ __align__(128) __nv_bfloat16 g_mlp [201326592];  // gelu(fc1) (bf16)
__device__ __align__(128) __nv_bfloat16 g_wq  [110592];
__device__ __align__(128) __nv_bfloat16 g_wp  [36864];
__device__ __align__(128) __nv_bfloat16 g_w1  [147456];
__device__ __align__(128) __nv_bfloat16 g_w2  [147456];

enum { EPI_QKV = 0, EPI_GELU = 1, EPI_PROJ = 2, EPI_FC2 = 3 };

// ---------------------------------------------------------------------------
__global__ __launch_bounds__(256) void k_cvt(
    const float* __restrict__ s, __nv_bfloat16* __restrict__ d, int n)
{
    int i = blockIdx.x * 256 + threadIdx.x;
    if (i < n) d[i] = __float2bfloat16(s[i]);
}

// ---------------------------------------------------------------------------
// K1: NCHW -> NHWC + LayerNorm1 + roll(-4,-4) + window partition (bf16 out)
// ---------------------------------------------------------------------------
__global__ __launch_bounds__(256) void k_pre(
    const float* __restrict__ x, const float* __restrict__ gam,
    const float* __restrict__ bet, float* __restrict__ xh,
    __nv_bfloat16* __restrict__ hout)
{
    __shared__ float tile[192][33];
    __shared__ float mean_s[32], rstd_s[32];
    int w0 = blockIdx.x * 32, hh = blockIdx.y, b = blockIdx.z;
    int tid = threadIdx.x;

    const float* xb = x + ((size_t)b * 192 * 256 + hh) * 256 + w0;
    for (int idx = tid; idx < 192 * 32; idx += 256) {
        int c = idx >> 5, wl = idx & 31;
        tile[c][wl] = xb[(size_t)c * 65536 + wl];
    }
    __syncthreads();

    {
        int wl = tid >> 3, j = tid & 7;
        float s = 0.f, s2 = 0.f;
        for (int c = j; c < 192; c += 8) { float v = tile[c][wl]; s += v; s2 += v * v; }
        #pragma unroll
        for (int o = 4; o > 0; o >>= 1) {
            s  += __shfl_xor_sync(0xffffffffu, s,  o, 8);
            s2 += __shfl_xor_sync(0xffffffffu, s2, o, 8);
        }
        if (j == 0) {
            float m = s * (1.f / 192.f);
            mean_s[wl] = m;
            rstd_s[wl] = rsqrtf(s2 * (1.f / 192.f) - m * m + 1e-5f);
        }
    }
    __syncthreads();

    int ir = (hh - 4) & 255;
    for (int idx = tid; idx < 192 * 32; idx += 256) {
        int wl = idx / 192, c = idx - wl * 192;
        int w = w0 + wl;
        float v = tile[c][wl];
        int sp = (b * 256 + hh) * 256 + w;
        xh[(size_t)sp * 192 + c] = v;
        float vn = (v - mean_s[wl]) * rstd_s[wl] * gam[c] + bet[c];
        int jr = (w - 4) & 255;
        int t = ((b * 32 + (ir >> 3)) * 32 + (jr >> 3)) * 64 + ((ir & 7) * 8 + (jr & 7));
        hout[(size_t)t * 192 + c] = __float2bfloat16(vn);
    }
}

// ---------------------------------------------------------------------------
// bf16 WMMA GEMM v2: C[M,N] = A[M,K] @ W[K,N] + bias, fused epilogues.
// BM=256, BN=64, BK=32; 8 warps (4m x 2n), warp tile 64x32 via 4x2 m16n16k16.
// 3-stage cp.async, one __syncthreads per K-iter. Dynamic smem (75264B).
// grid (N/64, M/256), 256 threads.
// ---------------------------------------------------------------------------
#define AST 40      // A smem row stride (halfs)
#define BST 72      // B smem row stride (halfs)
#define A_STAGE 20480
#define B_STAGE 4608
#define SMEM_BYTES (3 * A_STAGE + 3 * B_STAGE)   // 75264

template<int EPI>
__global__ __launch_bounds__(256, 2)
void gemm_bf16(const __nv_bfloat16* __restrict__ A, const __nv_bfloat16* __restrict__ W,
               const float* __restrict__ bias, void* __restrict__ Cout,
               int N, int K, const float* __restrict__ res)
{
    extern __shared__ __align__(16) char sm[];
    auto As = reinterpret_cast<__nv_bfloat16(*)[256][AST]>(sm);              // [3][256][40]
    auto Bs = reinterpret_cast<__nv_bfloat16(*)[32][BST]>(sm + 3 * A_STAGE); // [3][32][72]
    float (*Cs)[68] = reinterpret_cast<float(*)[68]>(sm);                    // 256x68x4 = 69632

    const int tid = threadIdx.x;
    const int mBase = blockIdx.y * 256, nBase = blockIdx.x * 64;
    const int warp = tid >> 5, wm = warp >> 1, wn = warp & 1;

    wmma::fragment<wmma::accumulator, 16, 16, 16, float> acc[4][2];
    #pragma unroll
    for (int i = 0; i < 4; i++)
        #pragma unroll
        for (int j = 0; j < 2; j++) wmma::fill_fragment(acc[i][j], 0.f);

    const int nk = K >> 5;

    auto load_tile = [&](int buf, int k0) {
        // A: thread tid loads its whole 32-half (64B) row slice: 4 x 16B
        const __nv_bfloat16* ap = &A[(size_t)(mBase + tid) * K + k0];
        #pragma unroll
        for (int u = 0; u < 4; u++)
            __pipeline_memcpy_async(&As[buf][tid][u * 8], ap + u * 8, 16);
        // B: 32 rows x 64 halfs = 256 x 16B chunks, 1/thread
        int r = tid >> 3, c = (tid & 7) << 3;
        __pipeline_memcpy_async(&Bs[buf][r][c], &W[(size_t)(k0 + r) * N + nBase + c], 16);
    };

    load_tile(0, 0);
    __pipeline_commit();
    load_tile(1, 32);
    __pipeline_commit();

    for (int it = 0; it < nk; ++it) {
        __pipeline_wait_prior(it == nk - 1 ? 0 : 1);
        __syncthreads();                       // tile `it` visible; all warps done with it-1
        int nx = it + 2;
        if (nx < nk) { load_tile(nx % 3, nx << 5); __pipeline_commit(); }

        int buf = it % 3;
        #pragma unroll
        for (int kk = 0; kk < 2; ++kk) {
            wmma::fragment<wmma::matrix_a, 16, 16, 16, __nv_bfloat16, wmma::row_major> af[4];
            wmma::fragment<wmma::matrix_b, 16, 16, 16, __nv_bfloat16, wmma::row_major> bf[2];
            #pragma unroll
            for (int i = 0; i < 4; i++)
                wmma::load_matrix_sync(af[i], &As[buf][wm * 64 + i * 16][kk * 16], AST);
            #pragma unroll
            for (int j = 0; j < 2; j++)
                wmma::load_matrix_sync(bf[j], &Bs[buf][kk * 16][wn * 32 + j * 16], BST);
            #pragma unroll
            for (int i = 0; i < 4; i++)
                #pragma unroll
                for (int j = 0; j < 2; j++)
                    wmma::mma_sync(acc[i][j], af[i], bf[j], acc[i][j]);
        }
    }
    __syncthreads();   // done with smem tiles; reuse as Cs

    #pragma unroll
    for (int i = 0; i < 4; i++)
        #pragma unroll
        for (int j = 0; j < 2; j++)
            wmma::store_matrix_sync(&Cs[wm * 64 + i * 16][wn * 32 + j * 16],
                                    acc[i][j], 68, wmma::mem_row_major);
    __syncthreads();

    if constexpr (EPI == EPI_FC2) {
        // pass 1 (row-major, coalesced res reads): bias + residual in smem
        for (int idx = tid; idx < 256 * 64; idx += 256) {
            int lr = idx >> 6, lc = idx & 63;
            Cs[lr][lc] += bias[nBase + lc] + res[(size_t)(mBase + lr) * 192 + nBase + lc];
        }
        __syncthreads();
        // pass 2 (col-major): coalesced NCHW writes to d_out
        float* out = (float*)Cout;
        for (int idx = tid; idx < 256 * 64; idx += 256) {
            int lc = idx >> 8, lr = idx & 255;
            int row = mBase + lr, col = nBase + lc;
            int b = row >> 16, hw = row & 65535;
            out[((size_t)(b * 192 + col) << 16) + hw] = Cs[lr][lc];
        }
    } else {
        for (int idx = tid; idx < 256 * 64; idx += 256) {
            int lr = idx >> 6, lc = idx & 63;
            int row = mBase + lr, col = nBase + lc;
            float vv = Cs[lr][lc] + bias[col];
            if constexpr (EPI == EPI_GELU) {
                vv = 0.5f * vv * (1.f + erff(vv * 0.70710678118654752f));
                ((__nv_bfloat16*)Cout)[(size_t)row * N + col] = __float2bfloat16(vv);
            } else if constexpr (EPI == EPI_PROJ) {
                int win = row >> 6, n = row & 63;
                int bb = win >> 10, wi = (win >> 5) & 31, wj = win & 31;
                int irr = wi * 8 + (n >> 3), jrr = wj * 8 + (n & 7);
                int i2 = (irr + 4) & 255, j2 = (jrr + 4) & 255;
                int sp = (bb * 256 + i2) * 256 + j2;
                vv += res[(size_t)sp * 192 + col];
                ((float*)Cout)[(size_t)sp * 192 + col] = vv;
            } else {  // EPI_QKV
                ((__nv_bfloat16*)Cout)[(size_t)row * N + col] = __float2bfloat16(vv);
            }
        }
    }
}

// ---------------------------------------------------------------------------
// K3: fused window attention. grid (4096 windows, 8 heads), 128 threads, fp32.
// ---------------------------------------------------------------------------
__global__ __launch_bounds__(128) void k_attn(
    const __nv_bfloat16* __restrict__ qkv, const float* __restrict__ rpb,
    __nv_bfloat16* __restrict__ out)
{
    __shared__ float q[64][25], kt[64][25], vt[64][25];
    __shared__ float S[64][65];
    __shared__ float rpb_s[225];
    __shared__ int cnt[64];

    int win = blockIdx.x, head = blockIdx.y, tid = threadIdx.x;

    for (int i = tid; i < 225; i += 128) rpb_s[i] = rpb[i * 8 + head];
    if (tid < 64) {
        int wi = (win >> 5) & 31, wj = win & 31;
        int ir = wi * 8 + (tid >> 3), jr = wj * 8 + (tid & 7);
        int gi = ir < 248 ? 0 : (ir < 252 ? 1 : 2);
        int gj = jr < 248 ? 0 : (jr < 252 ? 1 : 2);
        cnt[tid] = gi * 3 + gj;
    }

    const float scale = 0.20412414523193154f;   // 24^-0.5
    int base = win * 64 * 576 + head * 24;
    for (int idx = tid; idx < 64 * 24; idx += 128) {
        int n = idx / 24, d = idx - n * 24;
        int o = base + n * 576 + d;
        q[n][d]  = __bfloat162float(qkv[o]) * scale;
        kt[n][d] = __bfloat162float(qkv[o + 192]);
        vt[n][d] = __bfloat162float(qkv[o + 384]);
    }
    __syncthreads();

    int tr = tid >> 3, tc = tid & 7;
    float acc[4][8];
    #pragma unroll
    for (int i = 0; i < 4; i++)
        #pragma unroll
        for (int j = 0; j < 8; j++) acc[i][j] = 0.f;

    for (int d = 0; d < 24; d++) {
        float qv[4], kv[8];
        #pragma unroll
        for (int i = 0; i < 4; i++) qv[i] = q[tr + 16 * i][d];
        #pragma unroll
        for (int j = 0; j < 8; j++) kv[j] = kt[tc * 8 + j][d];
        #pragma unroll
        for (int i = 0; i < 4; i++)
            #pragma unroll
            for (int j = 0; j < 8; j++) acc[i][j] += qv[i] * kv[j];
    }
    #pragma unroll
    for (int i = 0; i < 4; i++) {
        int r = tr + 16 * i, rr = r >> 3, rc = r & 7;
        #pragma unroll
        for (int j = 0; j < 8; j++) {
            int c = tc * 8 + j, cr = c >> 3, cc = c & 7;
            float bv = rpb_s[(rr - cr + 7) * 15 + (rc - cc + 7)];
            float mv = (cnt[r] != cnt[c]) ? -100.f : 0.f;
            S[r][c] = acc[i][j] + bv + mv;
        }
    }
    __syncthreads();

    {   // softmax: 2 threads per row
        int row = tid >> 1, c0 = (tid & 1) * 32;
        float mx = -1e30f;
        #pragma unroll
        for (int j2 = 0; j2 < 32; j2++) mx = fmaxf(mx, S[row][c0 + j2]);
        mx = fmaxf(mx, __shfl_xor_sync(0xffffffffu, mx, 1));
        float sum = 0.f;
        #pragma unroll
        for (int j2 = 0; j2 < 32; j2++) {
            float e = __expf(S[row][c0 + j2] - mx);
            S[row][c0 + j2] = e;
            sum += e;
        }
        sum += __shfl_xor_sync(0xffffffffu, sum, 1);
        float inv = 1.f / sum;
        #pragma unroll
        for (int j2 = 0; j2 < 32; j2++) S[row][c0 + j2] *= inv;
    }
    __syncthreads();

    {   // AV: thread owns rows {r0+16i}, dims [tc*3, tc*3+3): 7 LDS / 12 FMA per m
        int r0 = tid >> 3, tcd = tid & 7, d0 = tcd * 3;
        float o[4][3];
        #pragma unroll
        for (int i = 0; i < 4; i++)
            #pragma unroll
            for (int dd = 0; dd < 3; dd++) o[i][dd] = 0.f;
        for (int m = 0; m < 64; m++) {
            float v0 = vt[m][d0], v1 = vt[m][d0 + 1], v2 = vt[m][d0 + 2];
            #pragma unroll
            for (int i = 0; i < 4; i++) {
                float p = S[r0 + 16 * i][m];
                o[i][0] += p * v0; o[i][1] += p * v1; o[i][2] += p * v2;
            }
        }
        #pragma unroll
        for (int i = 0; i < 4; i++) {
            int ob = (win * 64 + r0 + 16 * i) * 192 + head * 24 + d0;
            out[ob]     = __float2bfloat16(o[i][0]);
            out[ob + 1] = __float2bfloat16(o[i][1]);
            out[ob + 2] = __float2bfloat16(o[i][2]);
        }
    }
}

// ---------------------------------------------------------------------------
// K5: LayerNorm2 (one warp per token), bf16 out.
// ---------------------------------------------------------------------------
__global__ __launch_bounds__(256) void k_ln(
    const float* __restrict__ in, const float* __restrict__ gam,
    const float* __restrict__ bet, __nv_bfloat16* __restrict__ out)
{
    int warp = threadIdx.x >> 5, lane = threadIdx.x & 31;
    int row = blockIdx.x * 8 + warp;
    const float* r = in + (size_t)row * 192;
    float v[6];
    float s = 0.f, s2 = 0.f;
    #pragma unroll
    for (int i = 0; i < 6; i++) {
        v[i] = r[lane + 32 * i];
        s += v[i]; s2 += v[i] * v[i];
    }
    #pragma unroll
    for (int o = 16; o > 0; o >>= 1) {
        s  += __shfl_xor_sync(0xffffffffu, s,  o);
        s2 += __shfl_xor_sync(0xffffffffu, s2, o);
    }
    float m = s * (1.f / 192.f);
    float rstd = rsqrtf(s2 * (1.f / 192.f) - m * m + 1e-5f);
    __nv_bfloat16* o = out + (size_t)row * 192;
    #pragma unroll
    for (int i = 0; i < 6; i++) {
        int c = lane + 32 * i;
        o[c] = __float2bfloat16((v[i] - m) * rstd * gam[c] + bet[c]);
    }
}

// ---------------------------------------------------------------------------
extern "C" void kernel_launch(void* const* d_in, const int* in_sizes, int n_in,
                              void* d_out, int out_size)
{
    const float* x     = (const float*)d_in[0];
    const float* n1g   = (const float*)d_in[1];
    const float* n1b   = (const float*)d_in[2];
    const float* qkvw  = (const float*)d_in[3];
    const float* qkvb  = (const float*)d_in[4];
    const float* projw = (const float*)d_in[5];
    const float* projb = (const float*)d_in[6];
    const float* rpb   = (const float*)d_in[7];
    const float* n2g   = (const float*)d_in[8];
    const float* n2b   = (const float*)d_in[9];
    const float* fc1w  = (const float*)d_in[10];
    const float* fc1b  = (const float*)d_in[11];
    const float* fc2w  = (const float*)d_in[12];
    const float* fc2b  = (const float*)d_in[13];

    float *xh, *xh2;
    __nv_bfloat16 *h, *qkv, *attn, *mlp, *wq, *wp, *w1, *w2;
    cudaGetSymbolAddress((void**)&xh,   g_xh);
    cudaGetSymbolAddress((void**)&xh2,  g_xh2);
    cudaGetSymbolAddress((void**)&h,    g_h);
    cudaGetSymbolAddress((void**)&qkv,  g_qkv);
    cudaGetSymbolAddress((void**)&attn, g_attn);
    cudaGetSymbolAddress((void**)&mlp,  g_mlp);
    cudaGetSymbolAddress((void**)&wq,   g_wq);
    cudaGetSymbolAddress((void**)&wp,   g_wp);
    cudaGetSymbolAddress((void**)&w1,   g_w1);
    cudaGetSymbolAddress((void**)&w2,   g_w2);

    cudaFuncSetAttribute(gemm_bf16<EPI_QKV >, cudaFuncAttributeMaxDynamicSharedMemorySize, SMEM_BYTES);
    cudaFuncSetAttribute(gemm_bf16<EPI_PROJ>, cudaFuncAttributeMaxDynamicSharedMemorySize, SMEM_BYTES);
    cudaFuncSetAttribute(gemm_bf16<EPI_GELU>, cudaFuncAttributeMaxDynamicSharedMemorySize, SMEM_BYTES);
    cudaFuncSetAttribute(gemm_bf16<EPI_FC2 >, cudaFuncAttributeMaxDynamicSharedMemorySize, SMEM_BYTES);

    // 0. weight converts (tiny)
    k_cvt<<<(110592 + 255) / 256, 256>>>(qkvw, wq, 110592);
    k_cvt<<<(36864  + 255) / 256, 256>>>(projw, wp, 36864);
    k_cvt<<<(147456 + 255) / 256, 256>>>(fc1w,  w1, 147456);
    k_cvt<<<(147456 + 255) / 256, 256>>>(fc2w,  w2, 147456);

    // 1. transpose + LN1 + roll + window partition
    k_pre<<<dim3(8, 256, 4), 256>>>(x, n1g, n1b, xh, h);
    // 2. QKV GEMM
    gemm_bf16<EPI_QKV ><<<dim3(9, 1024),  256, SMEM_BYTES>>>(h,    wq, qkvb,  qkv,   576, 192, nullptr);
    // 3. window attention
    k_attn<<<dim3(4096, 8), 128>>>(qkv, rpb, attn);
    // 4. proj GEMM + window reverse + unroll + residual -> xh2 (fp32)
    gemm_bf16<EPI_PROJ><<<dim3(3, 1024),  256, SMEM_BYTES>>>(attn, wp, projb, xh2,   192, 192, xh);
    // 5. LN2 -> h (bf16)
    k_ln<<<32768, 256>>>(xh2, n2g, n2b, h);
    // 6. fc1 + GELU -> mlp (bf16)
    gemm_bf16<EPI_GELU><<<dim3(12, 1024), 256, SMEM_BYTES>>>(h,    w1, fc1b,  mlp,   768, 192, nullptr);
    // 7. fc2 + residual -> d_out (NCHW fp32, fused transpose)
    gemm_bf16<EPI_FC2 ><<<dim3(3, 1024),  256, SMEM_BYTES>>>(mlp,  w2, fc2b,  d_out, 192, 768, xh2);
}

// round 10
// speedup vs baseline: 1.6772x; 1.6772x over previous
#include <cuda_runtime.h>
#include <cuda_bf16.h>
#include <cuda_pipeline.h>
#include <mma.h>
using namespace nvcuda;

// ---------------------------------------------------------------------------
// Swin window-attention block, B=4, C=192, H=W=256, WS=8, SS=4, heads=8, hd=24
// bf16 tensor-core GEMMs (fp32 residual path).
// v3 GEMM: BM=128/BN=64/BK=32 (round-7 occupancy: 3 CTAs/SM), 3-stage
// cp.async pipeline with ONE barrier per K-iter.
// ---------------------------------------------------------------------------

// Scratch (device globals; no allocation at launch time)
__device__ __align__(128) float         g_xh  [50331648];   // shortcut (fp32), NHWC spatial
__device__ __align__(128) float         g_xh2 [50331648];   // x + attn (fp32), NHWC spatial
__device__ __align__(128) __nv_bfloat16 g_h   [50331648];   // LN'd activations (bf16)
__device__ __align__(128) __nv_bfloat16 g_qkv [150994944];  // qkv (bf16), window-token order
__device__ __align__(128) __nv_bfloat16 g_attn[50331648];   // attn out (bf16), window order
__device__ __align__(128) __nv_bfloat16 g_mlp [201326592];  // gelu(fc1) (bf16)
__device__ __align__(128) __nv_bfloat16 g_wq  [110592];
__device__ __align__(128) __nv_bfloat16 g_wp  [36864];
__device__ __align__(128) __nv_bfloat16 g_w1  [147456];
__device__ __align__(128) __nv_bfloat16 g_w2  [147456];

enum { EPI_QKV = 0, EPI_GELU = 1, EPI_PROJ = 2, EPI_FC2 = 3 };

// ---------------------------------------------------------------------------
__global__ __launch_bounds__(256) void k_cvt(
    const float* __restrict__ s, __nv_bfloat16* __restrict__ d, int n)
{
    int i = blockIdx.x * 256 + threadIdx.x;
    if (i < n) d[i] = __float2bfloat16(s[i]);
}

// ---------------------------------------------------------------------------
// K1: NCHW -> NHWC + LayerNorm1 + roll(-4,-4) + window partition (bf16 out)
// ---------------------------------------------------------------------------
__global__ __launch_bounds__(256) void k_pre(
    const float* __restrict__ x, const float* __restrict__ gam,
    const float* __restrict__ bet, float* __restrict__ xh,
    __nv_bfloat16* __restrict__ hout)
{
    __shared__ float tile[192][33];
    __shared__ float mean_s[32], rstd_s[32];
    int w0 = blockIdx.x * 32, hh = blockIdx.y, b = blockIdx.z;
    int tid = threadIdx.x;

    const float* xb = x + ((size_t)b * 192 * 256 + hh) * 256 + w0;
    for (int idx = tid; idx < 192 * 32; idx += 256) {
        int c = idx >> 5, wl = idx & 31;
        tile[c][wl] = xb[(size_t)c * 65536 + wl];
    }
    __syncthreads();

    {
        int wl = tid >> 3, j = tid & 7;
        float s = 0.f, s2 = 0.f;
        for (int c = j; c < 192; c += 8) { float v = tile[c][wl]; s += v; s2 += v * v; }
        #pragma unroll
        for (int o = 4; o > 0; o >>= 1) {
            s  += __shfl_xor_sync(0xffffffffu, s,  o, 8);
            s2 += __shfl_xor_sync(0xffffffffu, s2, o, 8);
        }
        if (j == 0) {
            float m = s * (1.f / 192.f);
            mean_s[wl] = m;
            rstd_s[wl] = rsqrtf(s2 * (1.f / 192.f) - m * m + 1e-5f);
        }
    }
    __syncthreads();

    int ir = (hh - 4) & 255;
    for (int idx = tid; idx < 192 * 32; idx += 256) {
        int wl = idx / 192, c = idx - wl * 192;
        int w = w0 + wl;
        float v = tile[c][wl];
        int sp = (b * 256 + hh) * 256 + w;
        xh[(size_t)sp * 192 + c] = v;
        float vn = (v - mean_s[wl]) * rstd_s[wl] * gam[c] + bet[c];
        int jr = (w - 4) & 255;
        int t = ((b * 32 + (ir >> 3)) * 32 + (jr >> 3)) * 64 + ((ir & 7) * 8 + (jr & 7));
        hout[(size_t)t * 192 + c] = __float2bfloat16(vn);
    }
}

// ---------------------------------------------------------------------------
// bf16 WMMA GEMM v3: C[M,N] = A[M,K] @ W[K,N] + bias, fused epilogues.
// BM=128, BN=64, BK=32; 8 warps (4m x 2n), warp tile 32x32 via 2x2 m16n16k16.
// 3-stage cp.async, ONE __syncthreads per K-iter. 3 CTAs/SM.
// grid (N/64, M/128), 256 threads.
// ---------------------------------------------------------------------------
#define AST 40      // A smem row stride (halfs)
#define BST 72      // B smem row stride (halfs)
#define A_STAGE 10240   // 128*40*2
#define B_STAGE 4608    // 32*72*2
#define SMEM_BYTES (3 * (A_STAGE + B_STAGE))   // 44544

template<int EPI>
__global__ __launch_bounds__(256, 3)
void gemm_bf16(const __nv_bfloat16* __restrict__ A, const __nv_bfloat16* __restrict__ W,
               const float* __restrict__ bias, void* __restrict__ Cout,
               int N, int K, const float* __restrict__ res)
{
    extern __shared__ __align__(16) char sm[];
    auto As = reinterpret_cast<__nv_bfloat16(*)[128][AST]>(sm);                  // [3][128][40]
    auto Bs = reinterpret_cast<__nv_bfloat16(*)[32][BST]>(sm + 3 * A_STAGE);     // [3][32][72]
    float (*Cs)[68] = reinterpret_cast<float(*)[68]>(sm);                        // 128x68x4=34816

    const int tid = threadIdx.x;
    const int mBase = blockIdx.y * 128, nBase = blockIdx.x * 64;
    const int warp = tid >> 5, wm = warp >> 1, wn = warp & 1;

    wmma::fragment<wmma::accumulator, 16, 16, 16, float> acc[2][2];
    #pragma unroll
    for (int i = 0; i < 2; i++)
        #pragma unroll
        for (int j = 0; j < 2; j++) wmma::fill_fragment(acc[i][j], 0.f);

    const int nk = K >> 5;

    auto load_tile = [&](int buf, int k0) {
        // A tile: 128 rows x 32 halfs = 512 x 16B chunks, 2/thread
        int f = tid << 1;
        {
            int r = f >> 2, c = (f & 3) << 3;
            __pipeline_memcpy_async(&As[buf][r][c],
                                    &A[(size_t)(mBase + r) * K + k0 + c], 16);
        }
        {
            int r = (f + 1) >> 2, c = ((f + 1) & 3) << 3;
            __pipeline_memcpy_async(&As[buf][r][c],
                                    &A[(size_t)(mBase + r) * K + k0 + c], 16);
        }
        // B tile: 32 rows x 64 halfs = 256 x 16B chunks, 1/thread
        int r = tid >> 3, c = (tid & 7) << 3;
        __pipeline_memcpy_async(&Bs[buf][r][c], &W[(size_t)(k0 + r) * N + nBase + c], 16);
    };

    load_tile(0, 0);
    __pipeline_commit();
    load_tile(1, 32);
    __pipeline_commit();

    for (int it = 0; it < nk; ++it) {
        __pipeline_wait_prior(it == nk - 1 ? 0 : 1);
        __syncthreads();            // tile `it` visible; all warps done with tile it-1
        int nx = it + 2;
        if (nx < nk) { load_tile(nx % 3, nx << 5); __pipeline_commit(); }

        int buf = it % 3;
        #pragma unroll
        for (int kk = 0; kk < 2; ++kk) {
            wmma::fragment<wmma::matrix_a, 16, 16, 16, __nv_bfloat16, wmma::row_major> af[2];
            wmma::fragment<wmma::matrix_b, 16, 16, 16, __nv_bfloat16, wmma::row_major> bf[2];
            wmma::load_matrix_sync(af[0], &As[buf][wm * 32][kk * 16], AST);
            wmma::load_matrix_sync(af[1], &As[buf][wm * 32 + 16][kk * 16], AST);
            wmma::load_matrix_sync(bf[0], &Bs[buf][kk * 16][wn * 32], BST);
            wmma::load_matrix_sync(bf[1], &Bs[buf][kk * 16][wn * 32 + 16], BST);
            #pragma unroll
            for (int i = 0; i < 2; i++)
                #pragma unroll
                for (int j = 0; j < 2; j++)
                    wmma::mma_sync(acc[i][j], af[i], bf[j], acc[i][j]);
        }
    }
    __syncthreads();   // done with smem tiles; reuse as Cs

    #pragma unroll
    for (int i = 0; i < 2; i++)
        #pragma unroll
        for (int j = 0; j < 2; j++)
            wmma::store_matrix_sync(&Cs[wm * 32 + i * 16][wn * 32 + j * 16],
                                    acc[i][j], 68, wmma::mem_row_major);
    __syncthreads();

    if constexpr (EPI == EPI_FC2) {
        // pass 1 (row-major, coalesced res reads): bias + residual in smem
        for (int idx = tid; idx < 128 * 64; idx += 256) {
            int lr = idx >> 6, lc = idx & 63;
            Cs[lr][lc] += bias[nBase + lc] + res[(size_t)(mBase + lr) * 192 + nBase + lc];
        }
        __syncthreads();
        // pass 2 (col-major): coalesced NCHW writes to d_out
        float* out = (float*)Cout;
        for (int idx = tid; idx < 128 * 64; idx += 256) {
            int lc = idx >> 7, lr = idx & 127;
            int row = mBase + lr, col = nBase + lc;
            int b = row >> 16, hw = row & 65535;
            out[((size_t)(b * 192 + col) << 16) + hw] = Cs[lr][lc];
        }
    } else {
        for (int idx = tid; idx < 128 * 64; idx += 256) {
            int lr = idx >> 6, lc = idx & 63;
            int row = mBase + lr, col = nBase + lc;
            float vv = Cs[lr][lc] + bias[col];
            if constexpr (EPI == EPI_GELU) {
                vv = 0.5f * vv * (1.f + erff(vv * 0.70710678118654752f));
                ((__nv_bfloat16*)Cout)[(size_t)row * N + col] = __float2bfloat16(vv);
            } else if constexpr (EPI == EPI_PROJ) {
                int win = row >> 6, n = row & 63;
                int bb = win >> 10, wi = (win >> 5) & 31, wj = win & 31;
                int irr = wi * 8 + (n >> 3), jrr = wj * 8 + (n & 7);
                int i2 = (irr + 4) & 255, j2 = (jrr + 4) & 255;
                int sp = (bb * 256 + i2) * 256 + j2;
                vv += res[(size_t)sp * 192 + col];
                ((float*)Cout)[(size_t)sp * 192 + col] = vv;
            } else {  // EPI_QKV
                ((__nv_bfloat16*)Cout)[(size_t)row * N + col] = __float2bfloat16(vv);
            }
        }
    }
}

// ---------------------------------------------------------------------------
// K3: fused window attention. grid (4096 windows, 8 heads), 128 threads, fp32.
// ---------------------------------------------------------------------------
__global__ __launch_bounds__(128) void k_attn(
    const __nv_bfloat16* __restrict__ qkv, const float* __restrict__ rpb,
    __nv_bfloat16* __restrict__ out)
{
    __shared__ float q[64][25], kt[64][25], vt[64][25];
    __shared__ float S[64][65];
    __shared__ float rpb_s[225];
    __shared__ int cnt[64];

    int win = blockIdx.x, head = blockIdx.y, tid = threadIdx.x;

    for (int i = tid; i < 225; i += 128) rpb_s[i] = rpb[i * 8 + head];
    if (tid < 64) {
        int wi = (win >> 5) & 31, wj = win & 31;
        int ir = wi * 8 + (tid >> 3), jr = wj * 8 + (tid & 7);
        int gi = ir < 248 ? 0 : (ir < 252 ? 1 : 2);
        int gj = jr < 248 ? 0 : (jr < 252 ? 1 : 2);
        cnt[tid] = gi * 3 + gj;
    }

    const float scale = 0.20412414523193154f;   // 24^-0.5
    int base = win * 64 * 576 + head * 24;
    for (int idx = tid; idx < 64 * 24; idx += 128) {
        int n = idx / 24, d = idx - n * 24;
        int o = base + n * 576 + d;
        q[n][d]  = __bfloat162float(qkv[o]) * scale;
        kt[n][d] = __bfloat162float(qkv[o + 192]);
        vt[n][d] = __bfloat162float(qkv[o + 384]);
    }
    __syncthreads();

    int tr = tid >> 3, tc = tid & 7;
    float acc[4][8];
    #pragma unroll
    for (int i = 0; i < 4; i++)
        #pragma unroll
        for (int j = 0; j < 8; j++) acc[i][j] = 0.f;

    for (int d = 0; d < 24; d++) {
        float qv[4], kv[8];
        #pragma unroll
        for (int i = 0; i < 4; i++) qv[i] = q[tr + 16 * i][d];
        #pragma unroll
        for (int j = 0; j < 8; j++) kv[j] = kt[tc * 8 + j][d];
        #pragma unroll
        for (int i = 0; i < 4; i++)
            #pragma unroll
            for (int j = 0; j < 8; j++) acc[i][j] += qv[i] * kv[j];
    }
    #pragma unroll
    for (int i = 0; i < 4; i++) {
        int r = tr + 16 * i, rr = r >> 3, rc = r & 7;
        #pragma unroll
        for (int j = 0; j < 8; j++) {
            int c = tc * 8 + j, cr = c >> 3, cc = c & 7;
            float bv = rpb_s[(rr - cr + 7) * 15 + (rc - cc + 7)];
            float mv = (cnt[r] != cnt[c]) ? -100.f : 0.f;
            S[r][c] = acc[i][j] + bv + mv;
        }
    }
    __syncthreads();

    {   // softmax: 2 threads per row
        int row = tid >> 1, c0 = (tid & 1) * 32;
        float mx = -1e30f;
        #pragma unroll
        for (int j2 = 0; j2 < 32; j2++) mx = fmaxf(mx, S[row][c0 + j2]);
        mx = fmaxf(mx, __shfl_xor_sync(0xffffffffu, mx, 1));
        float sum = 0.f;
        #pragma unroll
        for (int j2 = 0; j2 < 32; j2++) {
            float e = __expf(S[row][c0 + j2] - mx);
            S[row][c0 + j2] = e;
            sum += e;
        }
        sum += __shfl_xor_sync(0xffffffffu, sum, 1);
        float inv = 1.f / sum;
        #pragma unroll
        for (int j2 = 0; j2 < 32; j2++) S[row][c0 + j2] *= inv;
    }
    __syncthreads();

    {   // AV: thread owns rows {r0+16i}, dims [tc*3, tc*3+3)
        int r0 = tid >> 3, tcd = tid & 7, d0 = tcd * 3;
        float o[4][3];
        #pragma unroll
        for (int i = 0; i < 4; i++)
            #pragma unroll
            for (int dd = 0; dd < 3; dd++) o[i][dd] = 0.f;
        for (int m = 0; m < 64; m++) {
            float v0 = vt[m][d0], v1 = vt[m][d0 + 1], v2 = vt[m][d0 + 2];
            #pragma unroll
            for (int i = 0; i < 4; i++) {
                float p = S[r0 + 16 * i][m];
                o[i][0] += p * v0; o[i][1] += p * v1; o[i][2] += p * v2;
            }
        }
        #pragma unroll
        for (int i = 0; i < 4; i++) {
            int ob = (win * 64 + r0 + 16 * i) * 192 + head * 24 + d0;
            out[ob]     = __float2bfloat16(o[i][0]);
            out[ob + 1] = __float2bfloat16(o[i][1]);
            out[ob + 2] = __float2bfloat16(o[i][2]);
        }
    }
}

// ---------------------------------------------------------------------------
// K5: LayerNorm2 (one warp per token), bf16 out.
// ---------------------------------------------------------------------------
__global__ __launch_bounds__(256) void k_ln(
    const float* __restrict__ in, const float* __restrict__ gam,
    const float* __restrict__ bet, __nv_bfloat16* __restrict__ out)
{
    int warp = threadIdx.x >> 5, lane = threadIdx.x & 31;
    int row = blockIdx.x * 8 + warp;
    const float* r = in + (size_t)row * 192;
    float v[6];
    float s = 0.f, s2 = 0.f;
    #pragma unroll
    for (int i = 0; i < 6; i++) {
        v[i] = r[lane + 32 * i];
        s += v[i]; s2 += v[i] * v[i];
    }
    #pragma unroll
    for (int o = 16; o > 0; o >>= 1) {
        s  += __shfl_xor_sync(0xffffffffu, s,  o);
        s2 += __shfl_xor_sync(0xffffffffu, s2, o);
    }
    float m = s * (1.f / 192.f);
    float rstd = rsqrtf(s2 * (1.f / 192.f) - m * m + 1e-5f);
    __nv_bfloat16* o = out + (size_t)row * 192;
    #pragma unroll
    for (int i = 0; i < 6; i++) {
        int c = lane + 32 * i;
        o[c] = __float2bfloat16((v[i] - m) * rstd * gam[c] + bet[c]);
    }
}

// ---------------------------------------------------------------------------
extern "C" void kernel_launch(void* const* d_in, const int* in_sizes, int n_in,
                              void* d_out, int out_size)
{
    const float* x     = (const float*)d_in[0];
    const float* n1g   = (const float*)d_in[1];
    const float* n1b   = (const float*)d_in[2];
    const float* qkvw  = (const float*)d_in[3];
    const float* qkvb  = (const float*)d_in[4];
    const float* projw = (const float*)d_in[5];
    const float* projb = (const float*)d_in[6];
    const float* rpb   = (const float*)d_in[7];
    const float* n2g   = (const float*)d_in[8];
    const float* n2b   = (const float*)d_in[9];
    const float* fc1w  = (const float*)d_in[10];
    const float* fc1b  = (const float*)d_in[11];
    const float* fc2w  = (const float*)d_in[12];
    const float* fc2b  = (const float*)d_in[13];

    float *xh, *xh2;
    __nv_bfloat16 *h, *qkv, *attn, *mlp, *wq, *wp, *w1, *w2;
    cudaGetSymbolAddress((void**)&xh,   g_xh);
    cudaGetSymbolAddress((void**)&xh2,  g_xh2);
    cudaGetSymbolAddress((void**)&h,    g_h);
    cudaGetSymbolAddress((void**)&qkv,  g_qkv);
    cudaGetSymbolAddress((void**)&attn, g_attn);
    cudaGetSymbolAddress((void**)&mlp,  g_mlp);
    cudaGetSymbolAddress((void**)&wq,   g_wq);
    cudaGetSymbolAddress((void**)&wp,   g_wp);
    cudaGetSymbolAddress((void**)&w1,   g_w1);
    cudaGetSymbolAddress((void**)&w2,   g_w2);

    cudaFuncSetAttribute(gemm_bf16<EPI_QKV >, cudaFuncAttributeMaxDynamicSharedMemorySize, SMEM_BYTES);
    cudaFuncSetAttribute(gemm_bf16<EPI_PROJ>, cudaFuncAttributeMaxDynamicSharedMemorySize, SMEM_BYTES);
    cudaFuncSetAttribute(gemm_bf16<EPI_GELU>, cudaFuncAttributeMaxDynamicSharedMemorySize, SMEM_BYTES);
    cudaFuncSetAttribute(gemm_bf16<EPI_FC2 >, cudaFuncAttributeMaxDynamicSharedMemorySize, SMEM_BYTES);

    // 0. weight converts (tiny)
    k_cvt<<<(110592 + 255) / 256, 256>>>(qkvw, wq, 110592);
    k_cvt<<<(36864  + 255) / 256, 256>>>(projw, wp, 36864);
    k_cvt<<<(147456 + 255) / 256, 256>>>(fc1w,  w1, 147456);
    k_cvt<<<(147456 + 255) / 256, 256>>>(fc2w,  w2, 147456);

    // 1. transpose + LN1 + roll + window partition
    k_pre<<<dim3(8, 256, 4), 256>>>(x, n1g, n1b, xh, h);
    // 2. QKV GEMM
    gemm_bf16<EPI_QKV ><<<dim3(9, 2048),  256, SMEM_BYTES>>>(h,    wq, qkvb,  qkv,   576, 192, nullptr);
    // 3. window attention
    k_attn<<<dim3(4096, 8), 128>>>(qkv, rpb, attn);
    // 4. proj GEMM + window reverse + unroll + residual -> xh2 (fp32)
    gemm_bf16<EPI_PROJ><<<dim3(3, 2048),  256, SMEM_BYTES>>>(attn, wp, projb, xh2,   192, 192, xh);
    // 5. LN2 -> h (bf16)
    k_ln<<<32768, 256>>>(xh2, n2g, n2b, h);
    // 6. fc1 + GELU -> mlp (bf16)
    gemm_bf16<EPI_GELU><<<dim3(12, 2048), 256, SMEM_BYTES>>>(h,    w1, fc1b,  mlp,   768, 192, nullptr);
    // 7. fc2 + residual -> d_out (NCHW fp32, fused transpose)
    gemm_bf16<EPI_FC2 ><<<dim3(3, 2048),  256, SMEM_BYTES>>>(mlp,  w2, fc2b,  d_out, 192, 768, xh2);
}